// round 12
// baseline (speedup 1.0000x reference)
#include <cuda_runtime.h>
#include <math_constants.h>

// NDE loss, wave-quantization-free:
//   Kernel 1: exactly (#SMs * 8) CTAs, each owning one equal contiguous chunk
//   of the virtual concatenation [ori rows | gen rows] (row-major, V=50257
//   floats per row). A chunk spans <= 4 row-segments; per segment the block
//   computes a partial streaming logsumexp (float4 x4 per iter, __ldcs) and
//   writes (m, s) to g_part[row][slot]. Slot order is position-derived =>
//   deterministic combine.
//   Kernel 2: one block merges partials per row (fixed slot order), computes
//   lse + the row's contribution (entity gathers for gen rows, repeat-weighted
//   lse for ori rows), then reduces all per-row doubles in fixed order.
//
// out = (1/(N*E*T)) * sum_{n,t,e} ( gen[n,t,ent] - ori[rep[n],t,ent] )
//     + (1/(N*T))   * sum_{n,t}   ( lse_ori[rep[n],t] - lse_gen[n,t] )
//
// Bench shapes: B0=8, N=16, T=128, V=50257, E=4.

#define T_DIM 128
#define V_DIM 50257
#define NTHREADS 256
#define FIN_THREADS 1024
#define SLOTS 4
#define MAX_ROWS ((64 + 128) * T_DIM)

__device__ float  g_part_m[MAX_ROWS * SLOTS];
__device__ float  g_part_s[MAX_ROWS * SLOTS];
__device__ double g_contrib[MAX_ROWS];

// Merge two (m, s) logsumexp partials. Empty partial = (-inf, 0). The fmaxf
// clamp makes (-inf) - (-inf) = NaN resolve to a harmless tiny exponent.
__device__ __forceinline__ void lse_merge(float& m, float& s, float om, float os) {
    float nm = fmaxf(m, om);
    s = s * __expf(fmaxf(m - nm, -87.0f)) + os * __expf(fmaxf(om - nm, -87.0f));
    m = nm;
}

__device__ __forceinline__ float max4(float4 a) {
    return fmaxf(fmaxf(a.x, a.y), fmaxf(a.z, a.w));
}
__device__ __forceinline__ float expsum4(float4 a, float nm) {
    return __expf(a.x - nm) + __expf(a.y - nm) + __expf(a.z - nm) + __expf(a.w - nm);
}

// repeat_interleave(arange(B0), lens, total_repeat_length=N):
// truncate at N; pad with last element (B0-1) if sum < N.
__device__ __forceinline__ int rep_of(const int* lens, int B0, int N, int n) {
    int pre = 0;
    for (int b = 0; b < B0; b++) {
        int L = lens[b];
        if (n < pre + L) return b;
        pre += L;
    }
    return B0 - 1;
}

// ---------------------------------------------------------------------------
__global__ void __launch_bounds__(NTHREADS, 8)
lse_chunk_kernel(const float* __restrict__ ori, const float* __restrict__ gen,
                 int B0, long long total, long long chunk) {
    const long long gs = (long long)blockIdx.x * chunk;
    if (gs >= total) return;
    const long long ge = (gs + chunk < total) ? gs + chunk : total;

    const int r0 = (int)(gs / V_DIM);
    const int r1 = (int)((ge - 1) / V_DIM);
    const int oriRows = B0 * T_DIM;
    const int tid = threadIdx.x;
    const int B = NTHREADS;

    __shared__ float shm[NTHREADS / 32];
    __shared__ float shs[NTHREADS / 32];

    for (int r = r0; r <= r1; r++) {
        const long long rowStart = (long long)r * V_DIM;
        const int a = (r == r0) ? (int)(gs - rowStart) : 0;
        const int b = (r == r1) ? (int)(ge - rowStart) : V_DIM;
        const int len = b - a;
        const float* rowbase = (r < oriRows)
            ? ori + (size_t)r * V_DIM
            : gen + (size_t)(r - oriRows) * V_DIM;
        const float* p = rowbase + a;

        float m = -CUDART_INF_F;
        float s = 0.0f;

        // scalar peel to 16B alignment
        const int mis = (int)(((size_t)p >> 2) & 3u);
        const int pre = mis ? ((4 - mis) < len ? (4 - mis) : len) : 0;
        if (tid < pre) { m = p[tid]; s = 1.0f; }

        const int n4 = (len - pre) >> 2;
        const float4* __restrict__ p4 = reinterpret_cast<const float4*>(p + pre);

        int j = tid;
        for (; j + 3 * B < n4; j += 4 * B) {
            float4 x0 = __ldcs(&p4[j]);
            float4 x1 = __ldcs(&p4[j + B]);
            float4 x2 = __ldcs(&p4[j + 2 * B]);
            float4 x3 = __ldcs(&p4[j + 3 * B]);
            float lm = fmaxf(fmaxf(max4(x0), max4(x1)), fmaxf(max4(x2), max4(x3)));
            float nm = fmaxf(m, lm);
            s = s * __expf(m - nm)
                + expsum4(x0, nm) + expsum4(x1, nm)
                + expsum4(x2, nm) + expsum4(x3, nm);
            m = nm;
        }
        for (; j < n4; j += B) {
            float4 x0 = __ldcs(&p4[j]);
            float nm = fmaxf(m, max4(x0));
            s = s * __expf(m - nm) + expsum4(x0, nm);
            m = nm;
        }
        {
            const int done = pre + 4 * n4;
            const int rem = len - done;
            if (tid < rem) {
                float x = p[done + tid];
                float nm = fmaxf(m, x);
                s = s * __expf(m - nm) + __expf(x - nm);
                m = nm;
            }
        }

        // warp merge
        const unsigned full = 0xffffffffu;
        #pragma unroll
        for (int off = 16; off; off >>= 1) {
            float om = __shfl_xor_sync(full, m, off);
            float os = __shfl_xor_sync(full, s, off);
            lse_merge(m, s, om, os);
        }
        if ((tid & 31) == 0) { shm[tid >> 5] = m; shs[tid >> 5] = s; }
        __syncthreads();
        if (tid == 0) {
            float M = shm[0], S = shs[0];
            #pragma unroll
            for (int w = 1; w < NTHREADS / 32; w++) lse_merge(M, S, shm[w], shs[w]);
            int slot = blockIdx.x - (int)(rowStart / chunk);
            if (slot >= SLOTS) slot = SLOTS - 1;  // safety (never hit at bench shape)
            g_part_m[r * SLOTS + slot] = M;
            g_part_s[r * SLOTS + slot] = S;
        }
        __syncthreads();  // shm reuse across segments
    }
}

// ---------------------------------------------------------------------------
__global__ void __launch_bounds__(FIN_THREADS)
finalize_kernel(const float* __restrict__ ori, const float* __restrict__ gen,
                const int* __restrict__ lens, const int* __restrict__ ents,
                int B0, int N, int E, long long chunk, int totalRows,
                float* __restrict__ out) {
    const int tid = threadIdx.x;
    const int oriRows = B0 * T_DIM;
    const double invNT = 1.0 / ((double)N * (double)T_DIM);

    for (int r = tid; r < totalRows; r += FIN_THREADS) {
        const long long rowStart = (long long)r * V_DIM;
        const int c0 = (int)(rowStart / chunk);
        const int c1 = (int)((rowStart + V_DIM - 1) / chunk);

        float m = g_part_m[r * SLOTS];
        float s = g_part_s[r * SLOTS];
        for (int c = c0 + 1; c <= c1 && (c - c0) < SLOTS; c++) {
            lse_merge(m, s, g_part_m[r * SLOTS + (c - c0)],
                            g_part_s[r * SLOTS + (c - c0)]);
        }
        const double lse = (double)m + log((double)s);

        double contrib;
        if (r < oriRows) {
            // weight w_b = # of n with rep[n] == b (jnp pad-with-last)
            const int b = r / T_DIM;
            int pre = 0, w = 0;
            for (int k = 0; k < B0; k++) {
                int L = lens[k];
                if (k == b) {
                    int lo = pre < N ? pre : N;
                    int hi = (pre + L) < N ? (pre + L) : N;
                    w = hi - lo;
                }
                pre += L;
            }
            if (b == B0 - 1 && pre < N) w += N - pre;
            contrib = lse * (double)w * invNT;
        } else {
            const int rr = r - oriRows;
            const int n = rr / T_DIM;
            const int t = rr % T_DIM;
            const int rep = rep_of(lens, B0, N, n);
            const float* orow = ori + ((size_t)rep * T_DIM + t) * V_DIM;
            const float* grow = gen + ((size_t)n * T_DIM + t) * V_DIM;
            double ga = 0.0;
            for (int e = 0; e < E; e++) {
                int col = ents[n * E + e];
                ga += (double)grow[col] - (double)orow[col];
            }
            contrib = ga * invNT / (double)E - lse * invNT;
        }
        g_contrib[r] = contrib;
    }
    __syncthreads();

    // fixed-order deterministic reduction
    double acc = 0.0;
    for (int i = tid; i < totalRows; i += FIN_THREADS) acc += g_contrib[i];
    __shared__ double red[FIN_THREADS];
    red[tid] = acc;
    __syncthreads();
    #pragma unroll
    for (int off = FIN_THREADS / 2; off; off >>= 1) {
        if (tid < off) red[tid] += red[tid + off];
        __syncthreads();
    }
    if (tid == 0) out[0] = (float)red[0];
}

// ---------------------------------------------------------------------------
extern "C" void kernel_launch(void* const* d_in, const int* in_sizes, int n_in,
                              void* d_out, int out_size) {
    const float* ori  = (const float*)d_in[0];  // [B0, T, V]
    const float* gen  = (const float*)d_in[1];  // [N,  T, V]
    const int*   lens = (const int*)d_in[2];    // [B0]
    const int*   ents = (const int*)d_in[3];    // [N, E]

    const int B0 = in_sizes[0] / (T_DIM * V_DIM);
    const int N  = in_sizes[1] / (T_DIM * V_DIM);
    const int E  = in_sizes[3] / N;
    const int totalRows = (B0 + N) * T_DIM;
    const long long total = (long long)totalRows * V_DIM;

    int sms = 148;
    cudaDeviceGetAttribute(&sms, cudaDevAttrMultiProcessorCount, 0);
    const int nBlocks = sms * 8;  // exactly one wave at 8 CTAs/SM
    const long long chunk = (total + nBlocks - 1) / nBlocks;

    lse_chunk_kernel<<<nBlocks, NTHREADS>>>(ori, gen, B0, total, chunk);
    finalize_kernel<<<1, FIN_THREADS>>>(ori, gen, lens, ents, B0, N, E,
                                        chunk, totalRows, (float*)d_out);
}

// round 13
// speedup vs baseline: 1.0038x; 1.0038x over previous
#include <cuda_runtime.h>
#include <math_constants.h>

// NDE loss, wave-quantization-free:
//   Kernel 1: exactly (#SMs * 8) CTAs, each owning one equal contiguous chunk
//   of the virtual concatenation [ori rows | gen rows] (row-major, V=50257
//   floats per row). A chunk spans <= 4 row-segments; per segment the block
//   computes a partial streaming logsumexp (float4 x4 per iter, __ldcs) and
//   writes (m, s) to g_part[row][slot]. Slot order is position-derived =>
//   deterministic combine.
//   Kernel 2: one block merges partials per row (fixed slot order), computes
//   lse + the row's contribution (entity gathers for gen rows, repeat-weighted
//   lse for ori rows), then reduces all per-row doubles in fixed order.
//
// out = (1/(N*E*T)) * sum_{n,t,e} ( gen[n,t,ent] - ori[rep[n],t,ent] )
//     + (1/(N*T))   * sum_{n,t}   ( lse_ori[rep[n],t] - lse_gen[n,t] )
//
// Bench shapes: B0=8, N=16, T=128, V=50257, E=4.

#define T_DIM 128
#define V_DIM 50257
#define NTHREADS 256
#define FIN_THREADS 1024
#define SLOTS 4
#define MAX_ROWS ((64 + 128) * T_DIM)

__device__ float  g_part_m[MAX_ROWS * SLOTS];
__device__ float  g_part_s[MAX_ROWS * SLOTS];
__device__ double g_contrib[MAX_ROWS];

// Merge two (m, s) logsumexp partials. Empty partial = (-inf, 0). The fmaxf
// clamp makes (-inf) - (-inf) = NaN resolve to a harmless tiny exponent.
__device__ __forceinline__ void lse_merge(float& m, float& s, float om, float os) {
    float nm = fmaxf(m, om);
    s = s * __expf(fmaxf(m - nm, -87.0f)) + os * __expf(fmaxf(om - nm, -87.0f));
    m = nm;
}

__device__ __forceinline__ float max4(float4 a) {
    return fmaxf(fmaxf(a.x, a.y), fmaxf(a.z, a.w));
}
__device__ __forceinline__ float expsum4(float4 a, float nm) {
    return __expf(a.x - nm) + __expf(a.y - nm) + __expf(a.z - nm) + __expf(a.w - nm);
}

// repeat_interleave(arange(B0), lens, total_repeat_length=N):
// truncate at N; pad with last element (B0-1) if sum < N.
__device__ __forceinline__ int rep_of(const int* lens, int B0, int N, int n) {
    int pre = 0;
    for (int b = 0; b < B0; b++) {
        int L = lens[b];
        if (n < pre + L) return b;
        pre += L;
    }
    return B0 - 1;
}

// ---------------------------------------------------------------------------
__global__ void __launch_bounds__(NTHREADS, 8)
lse_chunk_kernel(const float* __restrict__ ori, const float* __restrict__ gen,
                 int B0, long long total, long long chunk) {
    const long long gs = (long long)blockIdx.x * chunk;
    if (gs >= total) return;
    const long long ge = (gs + chunk < total) ? gs + chunk : total;

    const int r0 = (int)(gs / V_DIM);
    const int r1 = (int)((ge - 1) / V_DIM);
    const int oriRows = B0 * T_DIM;
    const int tid = threadIdx.x;
    const int B = NTHREADS;

    __shared__ float shm[NTHREADS / 32];
    __shared__ float shs[NTHREADS / 32];

    for (int r = r0; r <= r1; r++) {
        const long long rowStart = (long long)r * V_DIM;
        const int a = (r == r0) ? (int)(gs - rowStart) : 0;
        const int b = (r == r1) ? (int)(ge - rowStart) : V_DIM;
        const int len = b - a;
        const float* rowbase = (r < oriRows)
            ? ori + (size_t)r * V_DIM
            : gen + (size_t)(r - oriRows) * V_DIM;
        const float* p = rowbase + a;

        float m = -CUDART_INF_F;
        float s = 0.0f;

        // scalar peel to 16B alignment
        const int mis = (int)(((size_t)p >> 2) & 3u);
        const int pre = mis ? ((4 - mis) < len ? (4 - mis) : len) : 0;
        if (tid < pre) { m = p[tid]; s = 1.0f; }

        const int n4 = (len - pre) >> 2;
        const float4* __restrict__ p4 = reinterpret_cast<const float4*>(p + pre);

        int j = tid;
        for (; j + 3 * B < n4; j += 4 * B) {
            float4 x0 = __ldcs(&p4[j]);
            float4 x1 = __ldcs(&p4[j + B]);
            float4 x2 = __ldcs(&p4[j + 2 * B]);
            float4 x3 = __ldcs(&p4[j + 3 * B]);
            float lm = fmaxf(fmaxf(max4(x0), max4(x1)), fmaxf(max4(x2), max4(x3)));
            float nm = fmaxf(m, lm);
            s = s * __expf(m - nm)
                + expsum4(x0, nm) + expsum4(x1, nm)
                + expsum4(x2, nm) + expsum4(x3, nm);
            m = nm;
        }
        for (; j < n4; j += B) {
            float4 x0 = __ldcs(&p4[j]);
            float nm = fmaxf(m, max4(x0));
            s = s * __expf(m - nm) + expsum4(x0, nm);
            m = nm;
        }
        {
            const int done = pre + 4 * n4;
            const int rem = len - done;
            if (tid < rem) {
                float x = p[done + tid];
                float nm = fmaxf(m, x);
                s = s * __expf(m - nm) + __expf(x - nm);
                m = nm;
            }
        }

        // warp merge
        const unsigned full = 0xffffffffu;
        #pragma unroll
        for (int off = 16; off; off >>= 1) {
            float om = __shfl_xor_sync(full, m, off);
            float os = __shfl_xor_sync(full, s, off);
            lse_merge(m, s, om, os);
        }
        if ((tid & 31) == 0) { shm[tid >> 5] = m; shs[tid >> 5] = s; }
        __syncthreads();
        if (tid == 0) {
            float M = shm[0], S = shs[0];
            #pragma unroll
            for (int w = 1; w < NTHREADS / 32; w++) lse_merge(M, S, shm[w], shs[w]);
            int slot = blockIdx.x - (int)(rowStart / chunk);
            if (slot >= SLOTS) slot = SLOTS - 1;  // safety (never hit at bench shape)
            g_part_m[r * SLOTS + slot] = M;
            g_part_s[r * SLOTS + slot] = S;
        }
        __syncthreads();  // shm reuse across segments
    }
}

// ---------------------------------------------------------------------------
__global__ void __launch_bounds__(FIN_THREADS)
finalize_kernel(const float* __restrict__ ori, const float* __restrict__ gen,
                const int* __restrict__ lens, const int* __restrict__ ents,
                int B0, int N, int E, long long chunk, int totalRows,
                float* __restrict__ out) {
    const int tid = threadIdx.x;
    const int oriRows = B0 * T_DIM;
    const double invNT = 1.0 / ((double)N * (double)T_DIM);

    for (int r = tid; r < totalRows; r += FIN_THREADS) {
        const long long rowStart = (long long)r * V_DIM;
        const int c0 = (int)(rowStart / chunk);
        const int c1 = (int)((rowStart + V_DIM - 1) / chunk);

        float m = g_part_m[r * SLOTS];
        float s = g_part_s[r * SLOTS];
        for (int c = c0 + 1; c <= c1 && (c - c0) < SLOTS; c++) {
            lse_merge(m, s, g_part_m[r * SLOTS + (c - c0)],
                            g_part_s[r * SLOTS + (c - c0)]);
        }
        const double lse = (double)m + log((double)s);

        double contrib;
        if (r < oriRows) {
            // weight w_b = # of n with rep[n] == b (jnp pad-with-last)
            const int b = r / T_DIM;
            int pre = 0, w = 0;
            for (int k = 0; k < B0; k++) {
                int L = lens[k];
                if (k == b) {
                    int lo = pre < N ? pre : N;
                    int hi = (pre + L) < N ? (pre + L) : N;
                    w = hi - lo;
                }
                pre += L;
            }
            if (b == B0 - 1 && pre < N) w += N - pre;
            contrib = lse * (double)w * invNT;
        } else {
            const int rr = r - oriRows;
            const int n = rr / T_DIM;
            const int t = rr % T_DIM;
            const int rep = rep_of(lens, B0, N, n);
            const float* orow = ori + ((size_t)rep * T_DIM + t) * V_DIM;
            const float* grow = gen + ((size_t)n * T_DIM + t) * V_DIM;
            double ga = 0.0;
            for (int e = 0; e < E; e++) {
                int col = ents[n * E + e];
                ga += (double)grow[col] - (double)orow[col];
            }
            contrib = ga * invNT / (double)E - lse * invNT;
        }
        g_contrib[r] = contrib;
    }
    __syncthreads();

    // fixed-order deterministic reduction
    double acc = 0.0;
    for (int i = tid; i < totalRows; i += FIN_THREADS) acc += g_contrib[i];
    __shared__ double red[FIN_THREADS];
    red[tid] = acc;
    __syncthreads();
    #pragma unroll
    for (int off = FIN_THREADS / 2; off; off >>= 1) {
        if (tid < off) red[tid] += red[tid + off];
        __syncthreads();
    }
    if (tid == 0) out[0] = (float)red[0];
}

// ---------------------------------------------------------------------------
extern "C" void kernel_launch(void* const* d_in, const int* in_sizes, int n_in,
                              void* d_out, int out_size) {
    const float* ori  = (const float*)d_in[0];  // [B0, T, V]
    const float* gen  = (const float*)d_in[1];  // [N,  T, V]
    const int*   lens = (const int*)d_in[2];    // [B0]
    const int*   ents = (const int*)d_in[3];    // [N, E]

    const int B0 = in_sizes[0] / (T_DIM * V_DIM);
    const int N  = in_sizes[1] / (T_DIM * V_DIM);
    const int E  = in_sizes[3] / N;
    const int totalRows = (B0 + N) * T_DIM;
    const long long total = (long long)totalRows * V_DIM;

    int sms = 148;
    cudaDeviceGetAttribute(&sms, cudaDevAttrMultiProcessorCount, 0);
    const int nBlocks = sms * 8;  // exactly one wave at 8 CTAs/SM
    const long long chunk = (total + nBlocks - 1) / nBlocks;

    lse_chunk_kernel<<<nBlocks, NTHREADS>>>(ori, gen, B0, total, chunk);
    finalize_kernel<<<1, FIN_THREADS>>>(ori, gen, lens, ents, B0, N, E,
                                        chunk, totalRows, (float*)d_out);
}

// round 14
// speedup vs baseline: 1.4117x; 1.4063x over previous
#include <cuda_runtime.h>
#include <math_constants.h>

// NDE loss, v4:
//   Kernel 1 (persistent, dynamic work-stealing): grid = #SMs*8 CTAs pull
//   row-quarter tiles (row r, quarter q; tile = V/4 ~ 12.5K floats ~ 50KB)
//   off a global atomic ticket. Per tile: streaming partial logsumexp
//   (float4 x4 per iter, __ldcs), block-reduced, written to
//   g_part[(r,q)]. Partials are keyed by POSITION, so the later merge order
//   is fixed => bitwise deterministic despite dynamic scheduling.
//   Kernel 2: one WARP per row (grid-parallel). Lane 0 merges the 4 quarter
//   partials (fixed order) and computes lse; lanes 0..2E-1 issue the entity
//   gathers concurrently; warp-reduce; per-row double contribution written.
//   Last block (fence + counter) reduces all rows in fixed order, writes the
//   scalar, and resets both global counters (graph-replay safe).
//
// out = (1/(N*E*T)) * sum_{n,t,e} ( gen[n,t,ent] - ori[rep[n],t,ent] )
//     + (1/(N*T))   * sum_{n,t}   ( lse_ori[rep[n],t] - lse_gen[n,t] )
//
// Bench shapes: B0=8, N=16, T=128, V=50257, E=4.

#define T_DIM 128
#define V_DIM 50257
#define NTHREADS 256
#define QUARTERS 4
#define MAX_ROWS ((64 + 128) * T_DIM)

__device__ float        g_part_m[MAX_ROWS * QUARTERS];
__device__ float        g_part_s[MAX_ROWS * QUARTERS];
__device__ double       g_contrib[MAX_ROWS];
__device__ unsigned int g_ticket;      // zero-init; reset by kernel 2
__device__ unsigned int g_done_count;  // zero-init; reset by kernel 2

__device__ __forceinline__ void lse_merge(float& m, float& s, float om, float os) {
    float nm = fmaxf(m, om);
    s = s * __expf(fmaxf(m - nm, -87.0f)) + os * __expf(fmaxf(om - nm, -87.0f));
    m = nm;
}
__device__ __forceinline__ float max4(float4 a) {
    return fmaxf(fmaxf(a.x, a.y), fmaxf(a.z, a.w));
}
__device__ __forceinline__ float expsum4(float4 a, float nm) {
    return __expf(a.x - nm) + __expf(a.y - nm) + __expf(a.z - nm) + __expf(a.w - nm);
}

// repeat_interleave(arange(B0), lens, total_repeat_length=N):
// truncate at N; pad with last element (B0-1) if sum < N.
__device__ __forceinline__ int rep_of(const int* lens, int B0, int N, int n) {
    int pre = 0;
    for (int b = 0; b < B0; b++) {
        int L = lens[b];
        if (n < pre + L) return b;
        pre += L;
    }
    return B0 - 1;
}

// ---------------------------------------------------------------------------
// Kernel 1: dynamic tile puller.
// ---------------------------------------------------------------------------
__global__ void __launch_bounds__(NTHREADS, 8)
lse_tile_kernel(const float* __restrict__ ori, const float* __restrict__ gen,
                int B0, int totalTiles) {
    const int tid = threadIdx.x;
    const int B = NTHREADS;
    const int oriRows = B0 * T_DIM;

    __shared__ int sh_tile;
    __shared__ float shm[NTHREADS / 32];
    __shared__ float shs[NTHREADS / 32];

    for (;;) {
        if (tid == 0) sh_tile = (int)atomicAdd(&g_ticket, 1u);
        __syncthreads();
        const int tile = sh_tile;
        if (tile >= totalTiles) return;

        const int r = tile >> 2;
        const int q = tile & 3;
        const int a = (V_DIM * q) >> 2;        // quarter start within row
        const int b = (V_DIM * (q + 1)) >> 2;  // quarter end
        const int len = b - a;

        const float* rowbase = (r < oriRows)
            ? ori + (size_t)r * V_DIM
            : gen + (size_t)(r - oriRows) * V_DIM;
        const float* p = rowbase + a;

        float m = -CUDART_INF_F;
        float s = 0.0f;

        // scalar peel to 16B alignment
        const int mis = (int)(((size_t)p >> 2) & 3u);
        const int pre = mis ? ((4 - mis) < len ? (4 - mis) : len) : 0;
        if (tid < pre) { m = p[tid]; s = 1.0f; }

        const int n4 = (len - pre) >> 2;
        const float4* __restrict__ p4 = reinterpret_cast<const float4*>(p + pre);

        int j = tid;
        for (; j + 3 * B < n4; j += 4 * B) {
            float4 x0 = __ldcs(&p4[j]);
            float4 x1 = __ldcs(&p4[j + B]);
            float4 x2 = __ldcs(&p4[j + 2 * B]);
            float4 x3 = __ldcs(&p4[j + 3 * B]);
            float lm = fmaxf(fmaxf(max4(x0), max4(x1)), fmaxf(max4(x2), max4(x3)));
            float nm = fmaxf(m, lm);
            s = s * __expf(m - nm)
                + expsum4(x0, nm) + expsum4(x1, nm)
                + expsum4(x2, nm) + expsum4(x3, nm);
            m = nm;
        }
        for (; j < n4; j += B) {
            float4 x0 = __ldcs(&p4[j]);
            float nm = fmaxf(m, max4(x0));
            s = s * __expf(m - nm) + expsum4(x0, nm);
            m = nm;
        }
        {
            const int done = pre + 4 * n4;
            const int rem = len - done;
            if (tid < rem) {
                float x = p[done + tid];
                float nm = fmaxf(m, x);
                s = s * __expf(m - nm) + __expf(x - nm);
                m = nm;
            }
        }

        // block reduce (m, s)
        const unsigned full = 0xffffffffu;
        #pragma unroll
        for (int off = 16; off; off >>= 1) {
            float om = __shfl_xor_sync(full, m, off);
            float os = __shfl_xor_sync(full, s, off);
            lse_merge(m, s, om, os);
        }
        if ((tid & 31) == 0) { shm[tid >> 5] = m; shs[tid >> 5] = s; }
        __syncthreads();
        if (tid == 0) {
            float M = shm[0], S = shs[0];
            #pragma unroll
            for (int w = 1; w < NTHREADS / 32; w++) lse_merge(M, S, shm[w], shs[w]);
            g_part_m[tile] = M;
            g_part_s[tile] = S;
        }
        __syncthreads();  // protect sh_tile/shm reuse next iteration
    }
}

// ---------------------------------------------------------------------------
// Kernel 2: one warp per row + last-block fixed-order reduction.
// ---------------------------------------------------------------------------
__global__ void __launch_bounds__(NTHREADS)
finalize_kernel(const float* __restrict__ ori, const float* __restrict__ gen,
                const int* __restrict__ lens, const int* __restrict__ ents,
                int B0, int N, int E, int totalRows, float* __restrict__ out) {
    const int tid = threadIdx.x;
    const int lane = tid & 31;
    const int row = blockIdx.x * (NTHREADS / 32) + (tid >> 5);
    const int oriRows = B0 * T_DIM;
    const double invNT = 1.0 / ((double)N * (double)T_DIM);
    const unsigned full = 0xffffffffu;
    __shared__ bool sh_last;

    if (row < totalRows) {
        // entity gathers: lanes 0..2E-1 load concurrently (gen rows only)
        double gval = 0.0;
        int n = 0, t = 0;
        const bool isGen = row >= oriRows;
        if (isGen) {
            const int rr = row - oriRows;
            n = rr / T_DIM;
            t = rr % T_DIM;
            if (lane < 2 * E) {
                const int e = (lane < E) ? lane : lane - E;
                const int col = ents[n * E + e];
                if (lane < E) {
                    gval = (double)gen[((size_t)n * T_DIM + t) * V_DIM + col];
                } else {
                    const int rep = rep_of(lens, B0, N, n);
                    gval = -(double)ori[((size_t)rep * T_DIM + t) * V_DIM + col];
                }
            }
        }
        // fixed-order warp sum of the 2E gathered values
        #pragma unroll
        for (int off = 16; off; off >>= 1)
            gval += __shfl_xor_sync(full, gval, off);

        if (lane == 0) {
            // merge quarter partials in fixed order
            float m = g_part_m[row * QUARTERS];
            float s = g_part_s[row * QUARTERS];
            #pragma unroll
            for (int q2 = 1; q2 < QUARTERS; q2++)
                lse_merge(m, s, g_part_m[row * QUARTERS + q2],
                                g_part_s[row * QUARTERS + q2]);
            const double lse = (double)m + log((double)s);

            double contrib;
            if (!isGen) {
                // weight w_b = # of n with rep[n]==b (jnp pad-with-last)
                const int b = row / T_DIM;
                int pre = 0, w = 0;
                for (int k = 0; k < B0; k++) {
                    int L = lens[k];
                    if (k == b) {
                        int lo = pre < N ? pre : N;
                        int hi = (pre + L) < N ? (pre + L) : N;
                        w = hi - lo;
                    }
                    pre += L;
                }
                if (b == B0 - 1 && pre < N) w += N - pre;
                contrib = lse * (double)w * invNT;
            } else {
                contrib = gval * invNT / (double)E - lse * invNT;
            }
            g_contrib[row] = contrib;
        }
    }

    __threadfence();
    __syncthreads();
    if (tid == 0) {
        unsigned prev = atomicAdd(&g_done_count, 1u);
        sh_last = (prev == gridDim.x - 1);
    }
    __syncthreads();

    if (sh_last) {
        double acc = 0.0;
        for (int i = tid; i < totalRows; i += NTHREADS) acc += g_contrib[i];
        __shared__ double red[NTHREADS];
        red[tid] = acc;
        __syncthreads();
        #pragma unroll
        for (int off = NTHREADS / 2; off; off >>= 1) {
            if (tid < off) red[tid] += red[tid + off];
            __syncthreads();
        }
        if (tid == 0) {
            out[0] = (float)red[0];
            g_done_count = 0;  // reset for graph replay
            g_ticket = 0;
        }
    }
}

// ---------------------------------------------------------------------------
extern "C" void kernel_launch(void* const* d_in, const int* in_sizes, int n_in,
                              void* d_out, int out_size) {
    const float* ori  = (const float*)d_in[0];  // [B0, T, V]
    const float* gen  = (const float*)d_in[1];  // [N,  T, V]
    const int*   lens = (const int*)d_in[2];    // [B0]
    const int*   ents = (const int*)d_in[3];    // [N, E]

    const int B0 = in_sizes[0] / (T_DIM * V_DIM);
    const int N  = in_sizes[1] / (T_DIM * V_DIM);
    const int E  = in_sizes[3] / N;
    const int totalRows = (B0 + N) * T_DIM;
    const int totalTiles = totalRows * QUARTERS;

    int sms = 148;
    cudaDeviceGetAttribute(&sms, cudaDevAttrMultiProcessorCount, 0);
    const int nBlocks = sms * 8;

    lse_tile_kernel<<<nBlocks, NTHREADS>>>(ori, gen, B0, totalTiles);
    const int finBlocks = (totalRows + (NTHREADS / 32) - 1) / (NTHREADS / 32);
    finalize_kernel<<<finBlocks, NTHREADS>>>(ori, gen, lens, ents, B0, N, E,
                                             totalRows, (float*)d_out);
}